// round 13
// baseline (speedup 1.0000x reference)
#include <cuda_runtime.h>
#include <cuda_fp16.h>
#include <cstdint>

#define NPTS   262144
#define NGRIDS 64
#define GS     64
#define CELLS  (GS*GS*GS)     // 262144
#define GPC    8              // grids per epoch (slab = 8 * 2.1MB, L2-resident)
#define NCHUNK (NGRIDS/GPC)   // 8
#define PBLK   (NPTS/256)     // 1024
#define NBINS  262144         // 64^3 spatial bins == grid cells
#define FSCALE 16384.0f
#define FINV   (1.0f/16384.0f)

// 8-byte chunk per (g,z,y,x): slot0 = half2(f0[x],f1[x])*FSCALE,
// slot1 = half2(f0[x+1],f1[x+1])*FSCALE (0 past the 63-edge).
__device__ uint2  g_pk[(size_t)NGRIDS * CELLS];   // 134 MB scratch
__device__ int    g_hist[NBINS];        // zero at load; scan re-zeroes
__device__ int    g_binStart[NBINS];
__device__ volatile int g_flag[256];    // lookback flags; scatter resets
__device__ float4 g_pxs[NPTS];          // sorted points: (x,y,z, bitcast(idx))

__device__ __forceinline__ void st64cs(void* p, uint2 v) {
    asm volatile("st.global.cs.v2.b32 [%0], {%1,%2};"
        :: "l"(p), "r"(v.x), "r"(v.y) : "memory");
}
__device__ __forceinline__ uint2 ld64nc(const void* p) {
    uint2 v;
    asm("ld.global.nc.v2.b32 {%0,%1}, [%2];" : "=r"(v.x), "=r"(v.y) : "l"(p));
    return v;
}
__device__ __forceinline__ void st256cs_f(void* p, const float* f) {
    asm volatile("st.global.cs.v8.f32 [%0], {%1,%2,%3,%4,%5,%6,%7,%8};"
        :: "l"(p), "f"(f[0]), "f"(f[1]), "f"(f[2]), "f"(f[3]),
           "f"(f[4]), "f"(f[5]), "f"(f[6]), "f"(f[7]) : "memory");
}

__device__ __forceinline__ int point_key(float tx, float ty, float tz) {
    int qx = min(max((int)((tx + 1.0f) * 32.0f), 0), 63);
    int qy = min(max((int)((ty + 1.0f) * 32.0f), 0), 63);
    int qz = min(max((int)((tz + 1.0f) * 32.0f), 0), 63);
    return (qz * GS + qy) * GS + qx;   // x fastest (matches chunk layout)
}

// ------------- launch 0: repack (fp16 x-pair chunks) + fused histogram ------
__global__ __launch_bounds__(256) void repack_hist_kernel(
    const float* __restrict__ fg, const float* __restrict__ xs)
{
    int idx = blockIdx.x * 256 + threadIdx.x;          // over NGRIDS*CELLS
    int g = idx >> 18;
    int c = idx & (CELLS - 1);
    int x = c & (GS - 1);
    const float* base = fg + (size_t)g * 2 * CELLS;    // [F=2, D, H, W]

    float a0 = base[c];
    float a1 = base[CELLS + c];
    float b0 = 0.0f, b1 = 0.0f;
    if (x < GS - 1) {
        b0 = base[c + 1];
        b1 = base[CELLS + c + 1];
    }
    __half2 h0 = __floats2half2_rn(a0 * FSCALE, a1 * FSCALE);
    __half2 h1 = __floats2half2_rn(b0 * FSCALE, b1 * FSCALE);
    uint2 v;
    v.x = *reinterpret_cast<unsigned*>(&h0);
    v.y = *reinterpret_cast<unsigned*>(&h1);
    st64cs(&g_pk[idx], v);

    if (idx < NPTS) {   // fused histogram (first 1024 blocks)
        atomicAdd(&g_hist[point_key(xs[idx*3], xs[idx*3+1], xs[idx*3+2])], 1);
    }
}

// ------------- launch 1: single-pass scan (decoupled lookback) --------------
// 256 blocks x 256 threads x 4 bins. Computes binStart (exclusive prefix),
// re-zeroes g_hist. Flags: value = (status<<28)|sum; 1=aggregate, 2=inclusive.
__global__ __launch_bounds__(256) void scan_kernel() {
    __shared__ int ws[8];
    __shared__ int s_base;
    int t = threadIdx.x;
    int lane = t & 31, w = t >> 5;
    int b = blockIdx.x;
    int i4 = (b * 256 + t) * 4;
    int4 v = *reinterpret_cast<const int4*>(&g_hist[i4]);
    *reinterpret_cast<int4*>(&g_hist[i4]) = make_int4(0, 0, 0, 0);  // re-zero
    int tot = v.x + v.y + v.z + v.w;
    int s = tot;
    #pragma unroll
    for (int o = 1; o < 32; o <<= 1) {
        int x = __shfl_up_sync(0xffffffffu, s, o);
        if (lane >= o) s += x;
    }
    if (lane == 31) ws[w] = s;
    __syncthreads();
    if (w == 0 && lane < 8) {
        int y = ws[lane];
        #pragma unroll
        for (int o = 1; o < 8; o <<= 1) {
            int x = __shfl_up_sync(0xffu, y, o);
            if (lane >= o) y += x;
        }
        ws[lane] = y;
    }
    __syncthreads();
    int blockTot = ws[7];

    if (t == 0) {
        if (b == 0) {
            g_flag[0] = (2 << 28) | blockTot;
            __threadfence();
            s_base = 0;
        } else {
            g_flag[b] = (1 << 28) | blockTot;   // publish aggregate
            __threadfence();
            int base = 0;
            int p = b - 1;
            while (true) {
                int f = g_flag[p];
                unsigned st = (unsigned)f >> 28;
                if (st == 0) continue;          // predecessor not ready
                base += f & 0x0FFFFFFF;
                if (st == 2u) break;            // inclusive found
                --p;
            }
            g_flag[b] = (2 << 28) | (base + blockTot);
            __threadfence();
            s_base = base;
        }
    }
    __syncthreads();

    int intra = ((w > 0) ? ws[w - 1] : 0) + s - tot;   // exclusive within block
    int base4 = s_base + intra;
    int4 o4;
    o4.x = base4;
    o4.y = base4 + v.x;
    o4.z = base4 + v.x + v.y;
    o4.w = base4 + v.x + v.y + v.z;
    *reinterpret_cast<int4*>(&g_binStart[i4]) = o4;
}

// ------------- launch 2: scatter (also resets lookback flags) ---------------
__global__ __launch_bounds__(256) void scatter_kernel(const float* __restrict__ xs) {
    int n = blockIdx.x * 256 + threadIdx.x;
    if (n < 256) g_flag[n] = 0;      // reset for next graph replay
    float tx = xs[n*3], ty = xs[n*3+1], tz = xs[n*3+2];
    int pos = atomicAdd(&g_binStart[point_key(tx, ty, tz)], 1);
    g_pxs[pos] = make_float4(tx, ty, tz, __int_as_float(n));
}

// ------------- launch 3: sample (profiled) ----------------------------------
__global__ __launch_bounds__(256) void sample_kernel(
    const float* __restrict__ M,      // [64, 4, 4]
    float* __restrict__ out)          // [NPTS, 128]
{
    __shared__ float sM[NGRIDS * 16];
    int tid = threadIdx.x;
    for (int i = tid; i < NGRIDS * 16; i += 256) {
        float v = M[i];
        sM[i] = ((i & 3) == 3) ? 31.5f * (v + 1.0f) : 31.5f * v;
    }
    __syncthreads();

    int chunk = blockIdx.x >> 10;              // grid epoch (L2-resident slab)
    int t     = (blockIdx.x & (PBLK - 1)) * 256 + tid;

    float4 p = g_pxs[t];                       // sorted -> warp-coherent gathers
    float tx = p.x, ty = p.y, tz = p.z;
    int n = __float_as_int(p.w);

    float res[2 * GPC];

    #pragma unroll
    for (int j = 0; j < GPC; ++j) {
        int g = chunk * GPC + j;
        const float* m = sM + g * 16;
        float px = fmaf(m[0], tx, fmaf(m[1], ty, fmaf(m[2],  tz, m[3])));
        float py = fmaf(m[4], tx, fmaf(m[5], ty, fmaf(m[6],  tz, m[7])));
        float pz = fmaf(m[8], tx, fmaf(m[9], ty, fmaf(m[10], tz, m[11])));

        float wx0, wx1, w00, w01, w10, w11;
        int r00, r01, r10, r11;

        bool interior = (px >= 0.0f) & (px < 63.0f) &
                        (py >= 0.0f) & (py < 63.0f) &
                        (pz >= 0.0f) & (pz < 63.0f);
        if (interior) {
            int ix = (int)px, iy = (int)py, iz = (int)pz;
            float fx = px - (float)ix;
            float fy = py - (float)iy;
            float fz = pz - (float)iz;
            wx0 = 1.0f - fx; wx1 = fx;
            float wz0 = (1.0f - fz) * FINV;
            float wz1 = fz * FINV;
            w00 = wz0 * (1.0f - fy); w01 = wz0 * fy;
            w10 = wz1 * (1.0f - fy); w11 = wz1 * fy;
            int b = (iz * GS + iy) * GS + ix;
            r00 = b;            r01 = b + GS;
            r10 = b + GS * GS;  r11 = b + GS * GS + GS;
        } else {
            float fx0 = floorf(px), fy0 = floorf(py), fz0 = floorf(pz);
            float fx = px - fx0, fy = py - fy0, fz = pz - fz0;
            int ix = (int)fx0, iy = (int)fy0, iz = (int)fz0;

            bool inx = ((unsigned)ix < 64u);
            wx0 = inx ? (1.0f - fx) : ((ix == -1) ? fx : 0.0f);
            wx1 = inx ? fx : 0.0f;
            int xc = min(max(ix, 0), 63);

            float wy0 = ((unsigned)iy       < 64u) ? (1.0f - fy) : 0.0f;
            float wy1 = ((unsigned)(iy + 1) < 64u) ? fy          : 0.0f;
            int iy0c = min(max(iy,     0), 63);
            int iy1c = min(max(iy + 1, 0), 63);

            float wz0 = ((unsigned)iz       < 64u) ? (1.0f - fz) * FINV : 0.0f;
            float wz1 = ((unsigned)(iz + 1) < 64u) ? fz          * FINV : 0.0f;
            int iz0c = min(max(iz,     0), 63);
            int iz1c = min(max(iz + 1, 0), 63);

            w00 = wz0 * wy0; w01 = wz0 * wy1;
            w10 = wz1 * wy0; w11 = wz1 * wy1;
            r00 = (iz0c * GS + iy0c) * GS + xc;
            r01 = (iz0c * GS + iy1c) * GS + xc;
            r10 = (iz1c * GS + iy0c) * GS + xc;
            r11 = (iz1c * GS + iy1c) * GS + xc;
        }

        const uint2* gp = g_pk + (size_t)g * CELLS;
        uint2 c00 = ld64nc(gp + r00);
        uint2 c01 = ld64nc(gp + r01);
        uint2 c10 = ld64nc(gp + r10);
        uint2 c11 = ld64nc(gp + r11);

        __half2 hx0 = __float2half2_rn(wx0);
        __half2 hx1 = __float2half2_rn(wx1);
        __half2 m00 = __hfma2(*reinterpret_cast<__half2*>(&c00.y), hx1,
                      __hmul2(*reinterpret_cast<__half2*>(&c00.x), hx0));
        __half2 m01 = __hfma2(*reinterpret_cast<__half2*>(&c01.y), hx1,
                      __hmul2(*reinterpret_cast<__half2*>(&c01.x), hx0));
        __half2 m10 = __hfma2(*reinterpret_cast<__half2*>(&c10.y), hx1,
                      __hmul2(*reinterpret_cast<__half2*>(&c10.x), hx0));
        __half2 m11 = __hfma2(*reinterpret_cast<__half2*>(&c11.y), hx1,
                      __hmul2(*reinterpret_cast<__half2*>(&c11.x), hx0));

        float2 f00 = __half22float2(m00);
        float2 f01 = __half22float2(m01);
        float2 f10 = __half22float2(m10);
        float2 f11 = __half22float2(m11);

        float a0 = f00.x * w00;
        a0 = fmaf(f01.x, w01, a0);
        a0 = fmaf(f10.x, w10, a0);
        a0 = fmaf(f11.x, w11, a0);
        float a1 = f00.y * w00;
        a1 = fmaf(f01.y, w01, a1);
        a1 = fmaf(f10.y, w10, a1);
        a1 = fmaf(f11.y, w11, a1);

        res[2 * j]     = a0;
        res[2 * j + 1] = a1;
    }

    float* op = out + (size_t)n * (NGRIDS * 2) + chunk * (GPC * 2);
    st256cs_f(op, res);
    st256cs_f(op + 8, res + 8);
}

extern "C" void kernel_launch(void* const* d_in, const int* in_sizes, int n_in,
                              void* d_out, int out_size)
{
    const float* xs = (const float*)d_in[0];   // [262144, 3]
    const float* M  = (const float*)d_in[1];   // [64, 4, 4]
    const float* fg = (const float*)d_in[2];   // [64, 2, 64, 64, 64]
    float* out = (float*)d_out;                // [262144, 128]

    repack_hist_kernel<<<(NGRIDS * CELLS) / 256, 256>>>(fg, xs);  // 0
    scan_kernel       <<<256, 256>>>();                            // 1
    scatter_kernel    <<<NPTS / 256, 256>>>(xs);                   // 2
    sample_kernel     <<<NCHUNK * PBLK, 256>>>(M, out);            // 3
}

// round 14
// speedup vs baseline: 1.0360x; 1.0360x over previous
#include <cuda_runtime.h>
#include <cuda_fp16.h>
#include <cstdint>

#define NPTS   262144
#define NGRIDS 64
#define GS     64
#define CELLS  (GS*GS*GS)     // 262144
#define GPC    8              // grids per epoch (slab = 8 * 2.1MB, L2-resident)
#define NCHUNK (NGRIDS/GPC)   // 8
#define PBLK   (NPTS/256)     // 1024
#define NBINS  262144         // 64^3 spatial bins == grid cells
#define FSCALE 16384.0f
#define FINV   (1.0f/16384.0f)

// 8-byte chunk per (g,z,y,x): slot0 = half2(f0[x],f1[x])*FSCALE,
// slot1 = half2(f0[x+1],f1[x+1])*FSCALE (0 past the 63-edge).
__device__ uint2  g_pk[(size_t)NGRIDS * CELLS];   // 134 MB scratch
__device__ int    g_hist[NBINS];        // zero at load; scan re-zeroes
__device__ int    g_binStart[NBINS];
__device__ volatile int g_flag[256];    // lookback flags; scatter resets
__device__ float4 g_pxs[NPTS];          // sorted points: (x,y,z, bitcast(idx))

__device__ __forceinline__ uint2 ld64nc(const void* p) {
    uint2 v;
    asm("ld.global.nc.v2.b32 {%0,%1}, [%2];" : "=r"(v.x), "=r"(v.y) : "l"(p));
    return v;
}
__device__ __forceinline__ void st128cs(void* p, uint4 v) {
    asm volatile("st.global.cs.v4.b32 [%0], {%1,%2,%3,%4};"
        :: "l"(p), "r"(v.x), "r"(v.y), "r"(v.z), "r"(v.w) : "memory");
}
__device__ __forceinline__ void st256cs_f(void* p, const float* f) {
    asm volatile("st.global.cs.v8.f32 [%0], {%1,%2,%3,%4,%5,%6,%7,%8};"
        :: "l"(p), "f"(f[0]), "f"(f[1]), "f"(f[2]), "f"(f[3]),
           "f"(f[4]), "f"(f[5]), "f"(f[6]), "f"(f[7]) : "memory");
}

__device__ __forceinline__ int point_key(float tx, float ty, float tz) {
    int qx = min(max((int)((tx + 1.0f) * 32.0f), 0), 63);
    int qy = min(max((int)((ty + 1.0f) * 32.0f), 0), 63);
    int qz = min(max((int)((tz + 1.0f) * 32.0f), 0), 63);
    return (qz * GS + qy) * GS + qx;   // x fastest (matches chunk layout)
}

// ------------- launch 0: histogram ------------------------------------------
__global__ __launch_bounds__(256) void hist_kernel(const float* __restrict__ xs) {
    int n = blockIdx.x * 256 + threadIdx.x;
    atomicAdd(&g_hist[point_key(xs[n*3], xs[n*3+1], xs[n*3+2])], 1);
}

// ------------- launch 1: single-pass scan (decoupled lookback) --------------
__global__ __launch_bounds__(256) void scan_kernel() {
    __shared__ int ws[8];
    __shared__ int s_base;
    int t = threadIdx.x;
    int lane = t & 31, w = t >> 5;
    int b = blockIdx.x;
    int i4 = (b * 256 + t) * 4;
    int4 v = *reinterpret_cast<const int4*>(&g_hist[i4]);
    *reinterpret_cast<int4*>(&g_hist[i4]) = make_int4(0, 0, 0, 0);  // re-zero
    int tot = v.x + v.y + v.z + v.w;
    int s = tot;
    #pragma unroll
    for (int o = 1; o < 32; o <<= 1) {
        int x = __shfl_up_sync(0xffffffffu, s, o);
        if (lane >= o) s += x;
    }
    if (lane == 31) ws[w] = s;
    __syncthreads();
    if (w == 0 && lane < 8) {
        int y = ws[lane];
        #pragma unroll
        for (int o = 1; o < 8; o <<= 1) {
            int x = __shfl_up_sync(0xffu, y, o);
            if (lane >= o) y += x;
        }
        ws[lane] = y;
    }
    __syncthreads();
    int blockTot = ws[7];

    if (t == 0) {
        if (b == 0) {
            g_flag[0] = (2 << 28) | blockTot;
            __threadfence();
            s_base = 0;
        } else {
            g_flag[b] = (1 << 28) | blockTot;
            __threadfence();
            int base = 0;
            int p = b - 1;
            while (true) {
                int f = g_flag[p];
                unsigned st = (unsigned)f >> 28;
                if (st == 0) continue;
                base += f & 0x0FFFFFFF;
                if (st == 2u) break;
                --p;
            }
            g_flag[b] = (2 << 28) | (base + blockTot);
            __threadfence();
            s_base = base;
        }
    }
    __syncthreads();

    int intra = ((w > 0) ? ws[w - 1] : 0) + s - tot;
    int base4 = s_base + intra;
    int4 o4;
    o4.x = base4;
    o4.y = base4 + v.x;
    o4.z = base4 + v.x + v.y;
    o4.w = base4 + v.x + v.y + v.z;
    *reinterpret_cast<int4*>(&g_binStart[i4]) = o4;
}

// ------------- launch 2: scatter (resets lookback flags) --------------------
__global__ __launch_bounds__(256) void scatter_kernel(const float* __restrict__ xs) {
    int n = blockIdx.x * 256 + threadIdx.x;
    if (n < 256) g_flag[n] = 0;
    float tx = xs[n*3], ty = xs[n*3+1], tz = xs[n*3+2];
    int pos = atomicAdd(&g_binStart[point_key(tx, ty, tz)], 1);
    g_pxs[pos] = make_float4(tx, ty, tz, __int_as_float(n));
}

// ------------- launch 3: repack, plane-staged (profiled) --------------------
// One block per (g,z) plane: stage both feature planes in shared (each gmem
// element read ONCE, coalesced float4), emit 2 chunks/iter as one STG.128
// (warp writes 512B contiguous).
__global__ __launch_bounds__(256) void repack_kernel(const float* __restrict__ fg)
{
    __shared__ float sf0[4096];
    __shared__ float sf1[4096];
    int gz = blockIdx.x;               // g*64 + z
    int g = gz >> 6, z = gz & 63;
    const float* p0 = fg + (size_t)g * 2 * CELLS + z * 4096;
    const float* p1 = p0 + CELLS;
    int t = threadIdx.x;

    #pragma unroll
    for (int k = 0; k < 4; ++k) {
        int i = k * 256 + t;           // float4 index (1024 per plane)
        float4 a = __ldg(reinterpret_cast<const float4*>(p0) + i);
        float4 b = __ldg(reinterpret_cast<const float4*>(p1) + i);
        *reinterpret_cast<float4*>(&sf0[i * 4]) = a;
        *reinterpret_cast<float4*>(&sf1[i * 4]) = b;
    }
    __syncthreads();

    uint2* outp = g_pk + (size_t)g * CELLS + z * 4096;
    #pragma unroll
    for (int k = 0; k < 8; ++k) {
        int c = k * 512 + t * 2;       // even cell; handles cells c, c+1
        float2 a0 = *reinterpret_cast<float2*>(&sf0[c]);   // f0[c], f0[c+1]
        float2 a1 = *reinterpret_cast<float2*>(&sf1[c]);   // f1[c], f1[c+1]
        bool v2 = ((c & 63) != 62);    // cell c+1 has in-row neighbor c+2?
        float n0 = v2 ? sf0[(c + 2) & 4095] : 0.0f;
        float n1 = v2 ? sf1[(c + 2) & 4095] : 0.0f;

        __half2 hA = __floats2half2_rn(a0.x * FSCALE, a1.x * FSCALE); // cell c
        __half2 hB = __floats2half2_rn(a0.y * FSCALE, a1.y * FSCALE); // cell c+1
        __half2 hC = __floats2half2_rn(n0 * FSCALE,  n1 * FSCALE);    // cell c+2

        uint4 o;
        o.x = *reinterpret_cast<unsigned*>(&hA);   // chunk c slot0
        o.y = *reinterpret_cast<unsigned*>(&hB);   // chunk c slot1 (x of c <= 62)
        o.z = o.y;                                 // chunk c+1 slot0
        o.w = *reinterpret_cast<unsigned*>(&hC);   // chunk c+1 slot1 (0 if edge)
        st128cs(outp + c, o);
    }
}

// ------------- launch 4: sample ----------------------------------------------
__global__ __launch_bounds__(256) void sample_kernel(
    const float* __restrict__ M,      // [64, 4, 4]
    float* __restrict__ out)          // [NPTS, 128]
{
    __shared__ float sM[NGRIDS * 16];
    int tid = threadIdx.x;
    for (int i = tid; i < NGRIDS * 16; i += 256) {
        float v = M[i];
        sM[i] = ((i & 3) == 3) ? 31.5f * (v + 1.0f) : 31.5f * v;
    }
    __syncthreads();

    int chunk = blockIdx.x >> 10;              // grid epoch (L2-resident slab)
    int t     = (blockIdx.x & (PBLK - 1)) * 256 + tid;

    float4 p = g_pxs[t];                       // sorted -> warp-coherent gathers
    float tx = p.x, ty = p.y, tz = p.z;
    int n = __float_as_int(p.w);

    float res[2 * GPC];

    #pragma unroll
    for (int j = 0; j < GPC; ++j) {
        int g = chunk * GPC + j;
        const float* m = sM + g * 16;
        float px = fmaf(m[0], tx, fmaf(m[1], ty, fmaf(m[2],  tz, m[3])));
        float py = fmaf(m[4], tx, fmaf(m[5], ty, fmaf(m[6],  tz, m[7])));
        float pz = fmaf(m[8], tx, fmaf(m[9], ty, fmaf(m[10], tz, m[11])));

        float wx0, wx1, w00, w01, w10, w11;
        int r00, r01, r10, r11;

        bool interior = (px >= 0.0f) & (px < 63.0f) &
                        (py >= 0.0f) & (py < 63.0f) &
                        (pz >= 0.0f) & (pz < 63.0f);
        if (interior) {
            int ix = (int)px, iy = (int)py, iz = (int)pz;
            float fx = px - (float)ix;
            float fy = py - (float)iy;
            float fz = pz - (float)iz;
            wx0 = 1.0f - fx; wx1 = fx;
            float wz0 = (1.0f - fz) * FINV;
            float wz1 = fz * FINV;
            w00 = wz0 * (1.0f - fy); w01 = wz0 * fy;
            w10 = wz1 * (1.0f - fy); w11 = wz1 * fy;
            int b = (iz * GS + iy) * GS + ix;
            r00 = b;            r01 = b + GS;
            r10 = b + GS * GS;  r11 = b + GS * GS + GS;
        } else {
            float fx0 = floorf(px), fy0 = floorf(py), fz0 = floorf(pz);
            float fx = px - fx0, fy = py - fy0, fz = pz - fz0;
            int ix = (int)fx0, iy = (int)fy0, iz = (int)fz0;

            bool inx = ((unsigned)ix < 64u);
            wx0 = inx ? (1.0f - fx) : ((ix == -1) ? fx : 0.0f);
            wx1 = inx ? fx : 0.0f;
            int xc = min(max(ix, 0), 63);

            float wy0 = ((unsigned)iy       < 64u) ? (1.0f - fy) : 0.0f;
            float wy1 = ((unsigned)(iy + 1) < 64u) ? fy          : 0.0f;
            int iy0c = min(max(iy,     0), 63);
            int iy1c = min(max(iy + 1, 0), 63);

            float wz0 = ((unsigned)iz       < 64u) ? (1.0f - fz) * FINV : 0.0f;
            float wz1 = ((unsigned)(iz + 1) < 64u) ? fz          * FINV : 0.0f;
            int iz0c = min(max(iz,     0), 63);
            int iz1c = min(max(iz + 1, 0), 63);

            w00 = wz0 * wy0; w01 = wz0 * wy1;
            w10 = wz1 * wy0; w11 = wz1 * wy1;
            r00 = (iz0c * GS + iy0c) * GS + xc;
            r01 = (iz0c * GS + iy1c) * GS + xc;
            r10 = (iz1c * GS + iy0c) * GS + xc;
            r11 = (iz1c * GS + iy1c) * GS + xc;
        }

        const uint2* gp = g_pk + (size_t)g * CELLS;
        uint2 c00 = ld64nc(gp + r00);
        uint2 c01 = ld64nc(gp + r01);
        uint2 c10 = ld64nc(gp + r10);
        uint2 c11 = ld64nc(gp + r11);

        __half2 hx0 = __float2half2_rn(wx0);
        __half2 hx1 = __float2half2_rn(wx1);
        __half2 m00 = __hfma2(*reinterpret_cast<__half2*>(&c00.y), hx1,
                      __hmul2(*reinterpret_cast<__half2*>(&c00.x), hx0));
        __half2 m01 = __hfma2(*reinterpret_cast<__half2*>(&c01.y), hx1,
                      __hmul2(*reinterpret_cast<__half2*>(&c01.x), hx0));
        __half2 m10 = __hfma2(*reinterpret_cast<__half2*>(&c10.y), hx1,
                      __hmul2(*reinterpret_cast<__half2*>(&c10.x), hx0));
        __half2 m11 = __hfma2(*reinterpret_cast<__half2*>(&c11.y), hx1,
                      __hmul2(*reinterpret_cast<__half2*>(&c11.x), hx0));

        float2 f00 = __half22float2(m00);
        float2 f01 = __half22float2(m01);
        float2 f10 = __half22float2(m10);
        float2 f11 = __half22float2(m11);

        float a0 = f00.x * w00;
        a0 = fmaf(f01.x, w01, a0);
        a0 = fmaf(f10.x, w10, a0);
        a0 = fmaf(f11.x, w11, a0);
        float a1 = f00.y * w00;
        a1 = fmaf(f01.y, w01, a1);
        a1 = fmaf(f10.y, w10, a1);
        a1 = fmaf(f11.y, w11, a1);

        res[2 * j]     = a0;
        res[2 * j + 1] = a1;
    }

    float* op = out + (size_t)n * (NGRIDS * 2) + chunk * (GPC * 2);
    st256cs_f(op, res);
    st256cs_f(op + 8, res + 8);
}

extern "C" void kernel_launch(void* const* d_in, const int* in_sizes, int n_in,
                              void* d_out, int out_size)
{
    const float* xs = (const float*)d_in[0];   // [262144, 3]
    const float* M  = (const float*)d_in[1];   // [64, 4, 4]
    const float* fg = (const float*)d_in[2];   // [64, 2, 64, 64, 64]
    float* out = (float*)d_out;                // [262144, 128]

    hist_kernel   <<<NPTS / 256, 256>>>(xs);          // 0
    scan_kernel   <<<256, 256>>>();                   // 1
    scatter_kernel<<<NPTS / 256, 256>>>(xs);          // 2
    repack_kernel <<<NGRIDS * GS, 256>>>(fg);         // 3 (profiled)
    sample_kernel <<<NCHUNK * PBLK, 256>>>(M, out);   // 4
}

// round 15
// speedup vs baseline: 1.0550x; 1.0183x over previous
#include <cuda_runtime.h>
#include <cuda_fp16.h>
#include <cstdint>

#define NPTS   262144
#define NGRIDS 64
#define GS     64
#define CELLS  (GS*GS*GS)     // 262144
#define GPC    8              // grids per epoch (slab = 8 * 2.1MB, L2-resident)
#define NCHUNK (NGRIDS/GPC)   // 8
#define PBLK   (NPTS/256)     // 1024
#define NBINS  262144         // 64^3 spatial bins == grid cells
#define FSCALE 16384.0f
#define FINV   (1.0f/16384.0f)

// 8-byte chunk per (g,z,y,x): slot0 = half2(f0[x],f1[x])*FSCALE,
// slot1 = half2(f0[x+1],f1[x+1])*FSCALE (0 past the 63-edge).
__device__ uint2  g_pk[(size_t)NGRIDS * CELLS];   // 134 MB scratch
__device__ int    g_hist[NBINS];        // zero at load; scan re-zeroes
__device__ int    g_binStart[NBINS];
__device__ volatile int g_flag[256];    // lookback flags; scatter resets
__device__ float4 g_pxs[NPTS];          // sorted points: (x,y,z, bitcast(idx))

__device__ __forceinline__ uint2 ld64nc(const void* p) {
    uint2 v;
    asm("ld.global.nc.v2.b32 {%0,%1}, [%2];" : "=r"(v.x), "=r"(v.y) : "l"(p));
    return v;
}
__device__ __forceinline__ void st128cs(void* p, uint4 v) {
    asm volatile("st.global.cs.v4.b32 [%0], {%1,%2,%3,%4};"
        :: "l"(p), "r"(v.x), "r"(v.y), "r"(v.z), "r"(v.w) : "memory");
}
__device__ __forceinline__ void st256cs_f(void* p, const float* f) {
    asm volatile("st.global.cs.v8.f32 [%0], {%1,%2,%3,%4,%5,%6,%7,%8};"
        :: "l"(p), "f"(f[0]), "f"(f[1]), "f"(f[2]), "f"(f[3]),
           "f"(f[4]), "f"(f[5]), "f"(f[6]), "f"(f[7]) : "memory");
}

__device__ __forceinline__ int point_key(float tx, float ty, float tz) {
    int qx = min(max((int)((tx + 1.0f) * 32.0f), 0), 63);
    int qy = min(max((int)((ty + 1.0f) * 32.0f), 0), 63);
    int qz = min(max((int)((tz + 1.0f) * 32.0f), 0), 63);
    return (qz * GS + qy) * GS + qx;   // x fastest (matches chunk layout)
}

// ------------- launch 0: repack (plane-staged) + balanced fused histogram ---
// One block per (g,z) plane; each block ALSO histograms 64 points (uniform
// extra work, atomics hidden under the DRAM-bound plane streaming).
__global__ __launch_bounds__(256) void repack_hist_kernel(
    const float* __restrict__ fg, const float* __restrict__ xs)
{
    __shared__ float sf0[4096];
    __shared__ float sf1[4096];
    int gz = blockIdx.x;               // g*64 + z
    int g = gz >> 6, z = gz & 63;
    const float* p0 = fg + (size_t)g * 2 * CELLS + z * 4096;
    const float* p1 = p0 + CELLS;
    int t = threadIdx.x;

    // fused histogram: 64 points per block (first 2 warps), issued first so
    // the atomic latency overlaps the plane loads below.
    if (t < 64) {
        int n = gz * 64 + t;
        float tx = xs[n*3], ty = xs[n*3+1], tz = xs[n*3+2];
        atomicAdd(&g_hist[point_key(tx, ty, tz)], 1);
    }

    #pragma unroll
    for (int k = 0; k < 4; ++k) {
        int i = k * 256 + t;           // float4 index (1024 per plane)
        float4 a = __ldg(reinterpret_cast<const float4*>(p0) + i);
        float4 b = __ldg(reinterpret_cast<const float4*>(p1) + i);
        *reinterpret_cast<float4*>(&sf0[i * 4]) = a;
        *reinterpret_cast<float4*>(&sf1[i * 4]) = b;
    }
    __syncthreads();

    uint2* outp = g_pk + (size_t)g * CELLS + z * 4096;
    #pragma unroll
    for (int k = 0; k < 8; ++k) {
        int c = k * 512 + t * 2;       // even cell; handles cells c, c+1
        float2 a0 = *reinterpret_cast<float2*>(&sf0[c]);   // f0[c], f0[c+1]
        float2 a1 = *reinterpret_cast<float2*>(&sf1[c]);   // f1[c], f1[c+1]
        bool v2 = ((c & 63) != 62);    // cell c+1 has in-row neighbor c+2?
        float n0 = v2 ? sf0[(c + 2) & 4095] : 0.0f;
        float n1 = v2 ? sf1[(c + 2) & 4095] : 0.0f;

        __half2 hA = __floats2half2_rn(a0.x * FSCALE, a1.x * FSCALE); // cell c
        __half2 hB = __floats2half2_rn(a0.y * FSCALE, a1.y * FSCALE); // cell c+1
        __half2 hC = __floats2half2_rn(n0 * FSCALE,  n1 * FSCALE);    // cell c+2

        uint4 o;
        o.x = *reinterpret_cast<unsigned*>(&hA);   // chunk c slot0
        o.y = *reinterpret_cast<unsigned*>(&hB);   // chunk c slot1
        o.z = o.y;                                 // chunk c+1 slot0
        o.w = *reinterpret_cast<unsigned*>(&hC);   // chunk c+1 slot1 (0 if edge)
        st128cs(outp + c, o);
    }
}

// ------------- launch 1: single-pass scan (decoupled lookback) --------------
__global__ __launch_bounds__(256) void scan_kernel() {
    __shared__ int ws[8];
    __shared__ int s_base;
    int t = threadIdx.x;
    int lane = t & 31, w = t >> 5;
    int b = blockIdx.x;
    int i4 = (b * 256 + t) * 4;
    int4 v = *reinterpret_cast<const int4*>(&g_hist[i4]);
    *reinterpret_cast<int4*>(&g_hist[i4]) = make_int4(0, 0, 0, 0);  // re-zero
    int tot = v.x + v.y + v.z + v.w;
    int s = tot;
    #pragma unroll
    for (int o = 1; o < 32; o <<= 1) {
        int x = __shfl_up_sync(0xffffffffu, s, o);
        if (lane >= o) s += x;
    }
    if (lane == 31) ws[w] = s;
    __syncthreads();
    if (w == 0 && lane < 8) {
        int y = ws[lane];
        #pragma unroll
        for (int o = 1; o < 8; o <<= 1) {
            int x = __shfl_up_sync(0xffu, y, o);
            if (lane >= o) y += x;
        }
        ws[lane] = y;
    }
    __syncthreads();
    int blockTot = ws[7];

    if (t == 0) {
        if (b == 0) {
            g_flag[0] = (2 << 28) | blockTot;
            __threadfence();
            s_base = 0;
        } else {
            g_flag[b] = (1 << 28) | blockTot;
            __threadfence();
            int base = 0;
            int p = b - 1;
            while (true) {
                int f = g_flag[p];
                unsigned st = (unsigned)f >> 28;
                if (st == 0) continue;
                base += f & 0x0FFFFFFF;
                if (st == 2u) break;
                --p;
            }
            g_flag[b] = (2 << 28) | (base + blockTot);
            __threadfence();
            s_base = base;
        }
    }
    __syncthreads();

    int intra = ((w > 0) ? ws[w - 1] : 0) + s - tot;
    int base4 = s_base + intra;
    int4 o4;
    o4.x = base4;
    o4.y = base4 + v.x;
    o4.z = base4 + v.x + v.y;
    o4.w = base4 + v.x + v.y + v.z;
    *reinterpret_cast<int4*>(&g_binStart[i4]) = o4;
}

// ------------- launch 2: scatter (resets lookback flags) --------------------
__global__ __launch_bounds__(256) void scatter_kernel(const float* __restrict__ xs) {
    int n = blockIdx.x * 256 + threadIdx.x;
    if (n < 256) g_flag[n] = 0;
    float tx = xs[n*3], ty = xs[n*3+1], tz = xs[n*3+2];
    int pos = atomicAdd(&g_binStart[point_key(tx, ty, tz)], 1);
    g_pxs[pos] = make_float4(tx, ty, tz, __int_as_float(n));
}

// ------------- launch 3: sample ----------------------------------------------
__global__ __launch_bounds__(256) void sample_kernel(
    const float* __restrict__ M,      // [64, 4, 4]
    float* __restrict__ out)          // [NPTS, 128]
{
    __shared__ float sM[NGRIDS * 16];
    int tid = threadIdx.x;
    for (int i = tid; i < NGRIDS * 16; i += 256) {
        float v = M[i];
        sM[i] = ((i & 3) == 3) ? 31.5f * (v + 1.0f) : 31.5f * v;
    }
    __syncthreads();

    int chunk = blockIdx.x >> 10;              // grid epoch (L2-resident slab)
    int t     = (blockIdx.x & (PBLK - 1)) * 256 + tid;

    float4 p = g_pxs[t];                       // sorted -> warp-coherent gathers
    float tx = p.x, ty = p.y, tz = p.z;
    int n = __float_as_int(p.w);

    float res[2 * GPC];

    #pragma unroll
    for (int j = 0; j < GPC; ++j) {
        int g = chunk * GPC + j;
        const float* m = sM + g * 16;
        float px = fmaf(m[0], tx, fmaf(m[1], ty, fmaf(m[2],  tz, m[3])));
        float py = fmaf(m[4], tx, fmaf(m[5], ty, fmaf(m[6],  tz, m[7])));
        float pz = fmaf(m[8], tx, fmaf(m[9], ty, fmaf(m[10], tz, m[11])));

        float wx0, wx1, w00, w01, w10, w11;
        int r00, r01, r10, r11;

        bool interior = (px >= 0.0f) & (px < 63.0f) &
                        (py >= 0.0f) & (py < 63.0f) &
                        (pz >= 0.0f) & (pz < 63.0f);
        if (interior) {
            int ix = (int)px, iy = (int)py, iz = (int)pz;
            float fx = px - (float)ix;
            float fy = py - (float)iy;
            float fz = pz - (float)iz;
            wx0 = 1.0f - fx; wx1 = fx;
            float wz0 = (1.0f - fz) * FINV;
            float wz1 = fz * FINV;
            w00 = wz0 * (1.0f - fy); w01 = wz0 * fy;
            w10 = wz1 * (1.0f - fy); w11 = wz1 * fy;
            int b = (iz * GS + iy) * GS + ix;
            r00 = b;            r01 = b + GS;
            r10 = b + GS * GS;  r11 = b + GS * GS + GS;
        } else {
            float fx0 = floorf(px), fy0 = floorf(py), fz0 = floorf(pz);
            float fx = px - fx0, fy = py - fy0, fz = pz - fz0;
            int ix = (int)fx0, iy = (int)fy0, iz = (int)fz0;

            bool inx = ((unsigned)ix < 64u);
            wx0 = inx ? (1.0f - fx) : ((ix == -1) ? fx : 0.0f);
            wx1 = inx ? fx : 0.0f;
            int xc = min(max(ix, 0), 63);

            float wy0 = ((unsigned)iy       < 64u) ? (1.0f - fy) : 0.0f;
            float wy1 = ((unsigned)(iy + 1) < 64u) ? fy          : 0.0f;
            int iy0c = min(max(iy,     0), 63);
            int iy1c = min(max(iy + 1, 0), 63);

            float wz0 = ((unsigned)iz       < 64u) ? (1.0f - fz) * FINV : 0.0f;
            float wz1 = ((unsigned)(iz + 1) < 64u) ? fz          * FINV : 0.0f;
            int iz0c = min(max(iz,     0), 63);
            int iz1c = min(max(iz + 1, 0), 63);

            w00 = wz0 * wy0; w01 = wz0 * wy1;
            w10 = wz1 * wy0; w11 = wz1 * wy1;
            r00 = (iz0c * GS + iy0c) * GS + xc;
            r01 = (iz0c * GS + iy1c) * GS + xc;
            r10 = (iz1c * GS + iy0c) * GS + xc;
            r11 = (iz1c * GS + iy1c) * GS + xc;
        }

        const uint2* gp = g_pk + (size_t)g * CELLS;
        uint2 c00 = ld64nc(gp + r00);
        uint2 c01 = ld64nc(gp + r01);
        uint2 c10 = ld64nc(gp + r10);
        uint2 c11 = ld64nc(gp + r11);

        __half2 hx0 = __float2half2_rn(wx0);
        __half2 hx1 = __float2half2_rn(wx1);
        __half2 m00 = __hfma2(*reinterpret_cast<__half2*>(&c00.y), hx1,
                      __hmul2(*reinterpret_cast<__half2*>(&c00.x), hx0));
        __half2 m01 = __hfma2(*reinterpret_cast<__half2*>(&c01.y), hx1,
                      __hmul2(*reinterpret_cast<__half2*>(&c01.x), hx0));
        __half2 m10 = __hfma2(*reinterpret_cast<__half2*>(&c10.y), hx1,
                      __hmul2(*reinterpret_cast<__half2*>(&c10.x), hx0));
        __half2 m11 = __hfma2(*reinterpret_cast<__half2*>(&c11.y), hx1,
                      __hmul2(*reinterpret_cast<__half2*>(&c11.x), hx0));

        float2 f00 = __half22float2(m00);
        float2 f01 = __half22float2(m01);
        float2 f10 = __half22float2(m10);
        float2 f11 = __half22float2(m11);

        float a0 = f00.x * w00;
        a0 = fmaf(f01.x, w01, a0);
        a0 = fmaf(f10.x, w10, a0);
        a0 = fmaf(f11.x, w11, a0);
        float a1 = f00.y * w00;
        a1 = fmaf(f01.y, w01, a1);
        a1 = fmaf(f10.y, w10, a1);
        a1 = fmaf(f11.y, w11, a1);

        res[2 * j]     = a0;
        res[2 * j + 1] = a1;
    }

    float* op = out + (size_t)n * (NGRIDS * 2) + chunk * (GPC * 2);
    st256cs_f(op, res);
    st256cs_f(op + 8, res + 8);
}

extern "C" void kernel_launch(void* const* d_in, const int* in_sizes, int n_in,
                              void* d_out, int out_size)
{
    const float* xs = (const float*)d_in[0];   // [262144, 3]
    const float* M  = (const float*)d_in[1];   // [64, 4, 4]
    const float* fg = (const float*)d_in[2];   // [64, 2, 64, 64, 64]
    float* out = (float*)d_out;                // [262144, 128]

    repack_hist_kernel<<<NGRIDS * GS, 256>>>(fg, xs);   // 0 (4096 blocks)
    scan_kernel       <<<256, 256>>>();                 // 1
    scatter_kernel    <<<NPTS / 256, 256>>>(xs);        // 2
    sample_kernel     <<<NCHUNK * PBLK, 256>>>(M, out); // 3
}